// round 1
// baseline (speedup 1.0000x reference)
#include <cuda_runtime.h>
#include <math.h>

#define BB 32
#define TT 4096
#define DD 512
#define UU 256

// scratch (no allocations allowed in kernel_launch)
__device__ float g_hq[BB * UU];       // query @ W2 + b2 + b1, per batch
__device__ float g_scores[BB * TT];   // logits, then overwritten with softmax weights

// ---------------------------------------------------------------------------
// hq[b][u] = sum_d query[b][d] * W2[d][u] + b2[u] + b1[u]
// grid = B, block = 256 (one thread per u)
// ---------------------------------------------------------------------------
__global__ void hq_kernel(const float* __restrict__ query,
                          const float* __restrict__ W2,
                          const float* __restrict__ b1,
                          const float* __restrict__ b2) {
    __shared__ float q[DD];
    const int b = blockIdx.x;
    const int u = threadIdx.x;
    for (int i = threadIdx.x; i < DD; i += blockDim.x) q[i] = query[b * DD + i];
    __syncthreads();
    float acc = b1[u] + b2[u];
#pragma unroll 8
    for (int d = 0; d < DD; ++d) acc = fmaf(q[d], W2[d * UU + u], acc);
    g_hq[b * UU + u] = acc;
}

// ---------------------------------------------------------------------------
// scores[b][t] = sum_u tanh( (values[b,t,:] @ W1[:,u]) + hq[b][u] ) * V[u]
// (bV dropped: constant shift cancels in softmax exactly)
// Tiled SGEMM: 128 t  x 128 u output tile per block, 8x8 per thread,
// K-chunks of 16 through shared memory. U covered in 2 chunks of 128,
// tanh*V epilogue folds accumulators straight into per-t partial scores.
// grid = (T/128, B), block = 256
// ---------------------------------------------------------------------------
__global__ __launch_bounds__(256, 2)
void scores_kernel(const float* __restrict__ values,
                   const float* __restrict__ W1,
                   const float* __restrict__ Vv) {
    __shared__ float As[16][132];   // [k][t], padded to dodge bank conflicts
    __shared__ float Bs[16][128];   // [k][u]

    const int b     = blockIdx.y;
    const int tbase = blockIdx.x * 128;
    const int tid   = threadIdx.x;
    const int tx    = tid & 15;     // u direction
    const int ty    = tid >> 4;     // t direction
    const int t0    = ty * 8;
    const int u0    = tx * 8;

    const float* vbase = values + ((size_t)b * TT + tbase) * DD;

    float spart[8];
#pragma unroll
    for (int i = 0; i < 8; ++i) spart[i] = 0.f;

    for (int uc = 0; uc < 2; ++uc) {
        float acc[8][8];
#pragma unroll
        for (int i = 0; i < 8; ++i)
#pragma unroll
            for (int j = 0; j < 8; ++j) acc[i][j] = 0.f;

        for (int k0 = 0; k0 < DD; k0 += 16) {
            // load A tile: 128 rows x 16 k  (512 float4, 2 per thread)
#pragma unroll
            for (int l = 0; l < 2; ++l) {
                const int f   = tid + l * 256;
                const int row = f >> 2;
                const int c4  = f & 3;
                const float4 v =
                    *(const float4*)(vbase + (size_t)row * DD + k0 + c4 * 4);
                As[c4 * 4 + 0][row] = v.x;
                As[c4 * 4 + 1][row] = v.y;
                As[c4 * 4 + 2][row] = v.z;
                As[c4 * 4 + 3][row] = v.w;
            }
            // load B tile: 16 k x 128 u  (512 float4, 2 per thread)
#pragma unroll
            for (int l = 0; l < 2; ++l) {
                const int f  = tid + l * 256;
                const int k  = f >> 5;
                const int c4 = f & 31;
                *(float4*)&Bs[k][c4 * 4] =
                    *(const float4*)(W1 + (size_t)(k0 + k) * UU + uc * 128 + c4 * 4);
            }
            __syncthreads();

#pragma unroll
            for (int kk = 0; kk < 16; ++kk) {
                float a[8], w[8];
                *(float4*)(a)     = *(const float4*)&As[kk][t0];
                *(float4*)(a + 4) = *(const float4*)&As[kk][t0 + 4];
                *(float4*)(w)     = *(const float4*)&Bs[kk][u0];
                *(float4*)(w + 4) = *(const float4*)&Bs[kk][u0 + 4];
#pragma unroll
                for (int i = 0; i < 8; ++i)
#pragma unroll
                    for (int j = 0; j < 8; ++j)
                        acc[i][j] = fmaf(a[i], w[j], acc[i][j]);
            }
            __syncthreads();
        }

        // epilogue: tanh + dot with V for this u-chunk
        const int ug = uc * 128 + u0;
        float hq[8], vv[8];
#pragma unroll
        for (int j = 0; j < 8; ++j) {
            hq[j] = g_hq[b * UU + ug + j];
            vv[j] = Vv[ug + j];
        }
#pragma unroll
        for (int i = 0; i < 8; ++i) {
            float s = 0.f;
#pragma unroll
            for (int j = 0; j < 8; ++j)
                s = fmaf(tanhf(acc[i][j] + hq[j]), vv[j], s);
            spart[i] += s;
        }
    }

    // reduce partial scores across the 16 tx lanes (xor < 16 stays in half-warp)
#pragma unroll
    for (int off = 8; off >= 1; off >>= 1)
#pragma unroll
        for (int i = 0; i < 8; ++i)
            spart[i] += __shfl_xor_sync(0xffffffffu, spart[i], off);

    if (tx == 0) {
#pragma unroll
        for (int i = 0; i < 8; ++i)
            g_scores[b * TT + tbase + t0 + i] = spart[i];
    }
}

// ---------------------------------------------------------------------------
// softmax over T per batch; weights overwrite g_scores (and go to wout if set)
// grid = B, block = 256
// ---------------------------------------------------------------------------
__global__ void softmax_kernel(float* __restrict__ wout) {
    __shared__ float red[8];
    __shared__ float bcast;
    const int b   = blockIdx.x;
    const int tid = threadIdx.x;
    float* s = g_scores + (size_t)b * TT;

    float m = -3.4e38f;
    for (int i = tid; i < TT; i += 256) m = fmaxf(m, s[i]);
#pragma unroll
    for (int off = 16; off; off >>= 1)
        m = fmaxf(m, __shfl_xor_sync(0xffffffffu, m, off));
    if ((tid & 31) == 0) red[tid >> 5] = m;
    __syncthreads();
    if (tid == 0) {
        float mm = red[0];
        for (int i = 1; i < 8; ++i) mm = fmaxf(mm, red[i]);
        bcast = mm;
    }
    __syncthreads();
    m = bcast;

    float sum = 0.f;
    for (int i = tid; i < TT; i += 256) {
        const float e = expf(s[i] - m);
        s[i] = e;
        sum += e;
    }
#pragma unroll
    for (int off = 16; off; off >>= 1)
        sum += __shfl_xor_sync(0xffffffffu, sum, off);
    if ((tid & 31) == 0) red[tid >> 5] = sum;
    __syncthreads();
    if (tid == 0) {
        float t = 0.f;
        for (int i = 0; i < 8; ++i) t += red[i];
        bcast = 1.f / t;
    }
    __syncthreads();
    const float inv = bcast;

    for (int i = tid; i < TT; i += 256) {
        const float wv = s[i] * inv;
        s[i] = wv;
        if (wout) wout[(size_t)b * TT + i] = wv;
    }
}

// ---------------------------------------------------------------------------
// context[b][d] = sum_t weights[b][t] * values[b][t][d]
// grid = (2 d-chunks, 8 t-splits, B), block = 256; atomicAdd into zeroed out.
// ---------------------------------------------------------------------------
__global__ void zero_ctx_kernel(float* __restrict__ ctx) {
    ctx[blockIdx.x * 256 + threadIdx.x] = 0.f;
}

__global__ void ctx_kernel(const float* __restrict__ values,
                           float* __restrict__ ctx) {
    const int b = blockIdx.z;
    const int d = blockIdx.x * 256 + threadIdx.x;
    const int tstart = blockIdx.y * (TT / 8);
    const float* vb = values + (size_t)b * TT * DD;
    const float* w  = g_scores + (size_t)b * TT;

    float acc = 0.f;
#pragma unroll 4
    for (int t = tstart; t < tstart + TT / 8; ++t)
        acc = fmaf(w[t], vb[(size_t)t * DD + d], acc);
    atomicAdd(&ctx[b * DD + d], acc);
}

// ---------------------------------------------------------------------------
extern "C" void kernel_launch(void* const* d_in, const int* in_sizes, int n_in,
                              void* d_out, int out_size) {
    const float* values = (const float*)d_in[0];
    const float* query  = (const float*)d_in[1];
    const float* W1     = (const float*)d_in[2];
    const float* b1     = (const float*)d_in[3];
    const float* W2     = (const float*)d_in[4];
    const float* b2     = (const float*)d_in[5];
    const float* Vv     = (const float*)d_in[6];
    // d_in[7] = bV: constant shift on all logits of a batch -> cancels in
    // softmax exactly; neither output depends on it.

    float* out  = (float*)d_out;
    float* ctx  = nullptr;
    float* wout = nullptr;
    if (out_size >= BB * DD + BB * TT) {        // context then weights
        ctx  = out;
        wout = out + BB * DD;
    } else if (out_size == BB * TT) {           // weights only
        wout = out;
    } else {                                    // context only
        ctx = out;
    }

    hq_kernel<<<BB, 256>>>(query, W2, b1, b2);
    scores_kernel<<<dim3(TT / 128, BB), 256>>>(values, W1, Vv);
    softmax_kernel<<<BB, 256>>>(wout);
    if (ctx) {
        zero_ctx_kernel<<<(BB * DD) / 256, 256>>>(ctx);
        ctx_kernel<<<dim3(2, 8, BB), 256>>>(values, ctx);
    }
}

// round 2
// speedup vs baseline: 1.7228x; 1.7228x over previous
#include <cuda_runtime.h>
#include <math.h>
#include <stdint.h>

#define BB 32
#define TT 4096
#define DD 512
#define UU 256

#define AP 36     // As pitch (floats): 128 rows(t) x 32 cols(k) + 4 pad
#define BP 264    // Bs pitch (floats): 32 rows(k) x 256 cols(u) + 8 pad

// scratch (no allocations allowed)
__device__ float g_hq[BB * UU];
__device__ float g_scores[BB * TT];

__device__ __forceinline__ uint32_t f2tf32(float f) {
    uint32_t r;
    asm("cvt.rna.tf32.f32 %0, %1;" : "=r"(r) : "f"(f));
    return r;
}

__device__ __forceinline__ void mma_tf32(float c[4], const uint32_t a[4],
                                         const uint32_t b[2]) {
    asm volatile(
        "mma.sync.aligned.m16n8k8.row.col.f32.tf32.tf32.f32 "
        "{%0,%1,%2,%3}, {%4,%5,%6,%7}, {%8,%9}, {%0,%1,%2,%3};"
        : "+f"(c[0]), "+f"(c[1]), "+f"(c[2]), "+f"(c[3])
        : "r"(a[0]), "r"(a[1]), "r"(a[2]), "r"(a[3]), "r"(b[0]), "r"(b[1]));
}

// ---------------------------------------------------------------------------
// hq[b][u] = query[b,:] @ W2[:,u] + b2[u] + b1[u]
// ---------------------------------------------------------------------------
__global__ void hq_kernel(const float* __restrict__ query,
                          const float* __restrict__ W2,
                          const float* __restrict__ b1,
                          const float* __restrict__ b2) {
    __shared__ float q[DD];
    const int b = blockIdx.x;
    const int u = threadIdx.x;
    for (int i = threadIdx.x; i < DD; i += blockDim.x) q[i] = query[b * DD + i];
    __syncthreads();
    float acc = b1[u] + b2[u];
#pragma unroll 8
    for (int d = 0; d < DD; ++d) acc = fmaf(q[d], W2[d * UU + u], acc);
    g_hq[b * UU + u] = acc;
}

// ---------------------------------------------------------------------------
// scores[b][t] = sum_u tanh( values[b,t,:]@W1[:,u] + hq[b][u] ) * V[u]
// Tensor-core GEMM: one block = 128t x 256u full tile, tf32 mma.m16n8k8.
// 512 threads = 16 warps arranged 2(M) x 8(N); per warp M=64 (4 m16 tiles),
// N=32 (4 n8 tiles). values streamed through smem ONCE (K-chunks of 32).
// tanh*V epilogue on register fragments + shfl/smem reduction.
// grid = (T/128, B), block = 512, dynamic smem 52.7KB
// ---------------------------------------------------------------------------
__global__ __launch_bounds__(512, 1)
void scores_mma(const float* __restrict__ values,
                const float* __restrict__ W1,
                const float* __restrict__ Vv) {
    extern __shared__ float sm[];
    float* As   = sm;                   // [128][AP]
    float* Bs   = sm + 128 * AP;        // [32][BP]
    float* sred = Bs + 32 * BP;         // [128]

    const int b     = blockIdx.y;
    const int tbase = blockIdx.x * 128;
    const int tid   = threadIdx.x;
    const int lane  = tid & 31;
    const int wid   = tid >> 5;
    const int wm    = wid & 1;          // warp row (M):   2 x 64 t
    const int wn    = wid >> 1;         // warp col (N):   8 x 32 u
    const int g     = lane >> 2;        // groupID
    const int tg    = lane & 3;         // threadID in group

    const float* vbase = values + ((size_t)b * TT + tbase) * DD;

    float acc[4][4][4];                 // [m-tile][n-tile][frag]
#pragma unroll
    for (int i = 0; i < 4; ++i)
#pragma unroll
        for (int j = 0; j < 4; ++j)
#pragma unroll
            for (int c = 0; c < 4; ++c) acc[i][j][c] = 0.f;

    for (int k0 = 0; k0 < DD; k0 += 32) {
        __syncthreads();
        // stage A (values) 128t x 32k : 1024 float4, 2 per thread
#pragma unroll
        for (int l = 0; l < 2; ++l) {
            const int idx = tid + l * 512;
            const int t   = idx >> 3;
            const int k4  = idx & 7;
            const float4 v =
                *(const float4*)(vbase + (size_t)t * DD + k0 + k4 * 4);
            float4 o;
            o.x = __uint_as_float(f2tf32(v.x));
            o.y = __uint_as_float(f2tf32(v.y));
            o.z = __uint_as_float(f2tf32(v.z));
            o.w = __uint_as_float(f2tf32(v.w));
            *(float4*)&As[t * AP + k4 * 4] = o;
        }
        // stage B (W1) 32k x 256u : 2048 float4, 4 per thread
#pragma unroll
        for (int l = 0; l < 4; ++l) {
            const int idx = tid + l * 512;
            const int k   = idx >> 6;
            const int u4  = idx & 63;
            const float4 v =
                *(const float4*)(W1 + (size_t)(k0 + k) * UU + u4 * 4);
            float4 o;
            o.x = __uint_as_float(f2tf32(v.x));
            o.y = __uint_as_float(f2tf32(v.y));
            o.z = __uint_as_float(f2tf32(v.z));
            o.w = __uint_as_float(f2tf32(v.w));
            *(float4*)&Bs[k * BP + u4 * 4] = o;
        }
        __syncthreads();

#pragma unroll
        for (int ks = 0; ks < 4; ++ks) {
            const int kk = ks * 8;
            uint32_t a[4][4];
#pragma unroll
            for (int mi = 0; mi < 4; ++mi) {
                const int row = wm * 64 + mi * 16 + g;
                a[mi][0] = __float_as_uint(As[row * AP + kk + tg]);
                a[mi][1] = __float_as_uint(As[(row + 8) * AP + kk + tg]);
                a[mi][2] = __float_as_uint(As[row * AP + kk + 4 + tg]);
                a[mi][3] = __float_as_uint(As[(row + 8) * AP + kk + 4 + tg]);
            }
            uint32_t bf[4][2];
#pragma unroll
            for (int nj = 0; nj < 4; ++nj) {
                const int u = wn * 32 + nj * 8 + g;
                bf[nj][0] = __float_as_uint(Bs[(kk + tg) * BP + u]);
                bf[nj][1] = __float_as_uint(Bs[(kk + 4 + tg) * BP + u]);
            }
#pragma unroll
            for (int mi = 0; mi < 4; ++mi)
#pragma unroll
                for (int nj = 0; nj < 4; ++nj)
                    mma_tf32(acc[mi][nj], a[mi], bf[nj]);
        }
    }

    // epilogue: tanh + dot with V, reduce over u
    float sp[4][2];
#pragma unroll
    for (int mi = 0; mi < 4; ++mi) { sp[mi][0] = 0.f; sp[mi][1] = 0.f; }

#pragma unroll
    for (int nj = 0; nj < 4; ++nj) {
        const int u0  = wn * 32 + nj * 8 + 2 * tg;
        const float h0 = g_hq[b * UU + u0];
        const float h1 = g_hq[b * UU + u0 + 1];
        const float v0 = Vv[u0];
        const float v1 = Vv[u0 + 1];
#pragma unroll
        for (int mi = 0; mi < 4; ++mi) {
            sp[mi][0] = fmaf(tanhf(acc[mi][nj][0] + h0), v0, sp[mi][0]);
            sp[mi][0] = fmaf(tanhf(acc[mi][nj][1] + h1), v1, sp[mi][0]);
            sp[mi][1] = fmaf(tanhf(acc[mi][nj][2] + h0), v0, sp[mi][1]);
            sp[mi][1] = fmaf(tanhf(acc[mi][nj][3] + h1), v1, sp[mi][1]);
        }
    }
    // reduce across the 4 lanes of each group (cols)
#pragma unroll
    for (int off = 1; off <= 2; off <<= 1)
#pragma unroll
        for (int mi = 0; mi < 4; ++mi) {
            sp[mi][0] += __shfl_xor_sync(0xffffffffu, sp[mi][0], off);
            sp[mi][1] += __shfl_xor_sync(0xffffffffu, sp[mi][1], off);
        }

    if (tid < 128) sred[tid] = 0.f;
    __syncthreads();
    if (tg == 0) {
#pragma unroll
        for (int mi = 0; mi < 4; ++mi) {
            atomicAdd(&sred[wm * 64 + mi * 16 + g],     sp[mi][0]);
            atomicAdd(&sred[wm * 64 + mi * 16 + g + 8], sp[mi][1]);
        }
    }
    __syncthreads();
    if (tid < 128) g_scores[(size_t)b * TT + tbase + tid] = sred[tid];
}

// ---------------------------------------------------------------------------
// softmax over T per batch
// ---------------------------------------------------------------------------
__global__ void softmax_kernel(float* __restrict__ wout) {
    __shared__ float red[8];
    __shared__ float bcast;
    const int b   = blockIdx.x;
    const int tid = threadIdx.x;
    float* s = g_scores + (size_t)b * TT;

    float m = -3.4e38f;
    for (int i = tid; i < TT; i += 256) m = fmaxf(m, s[i]);
#pragma unroll
    for (int off = 16; off; off >>= 1)
        m = fmaxf(m, __shfl_xor_sync(0xffffffffu, m, off));
    if ((tid & 31) == 0) red[tid >> 5] = m;
    __syncthreads();
    if (tid == 0) {
        float mm = red[0];
        for (int i = 1; i < 8; ++i) mm = fmaxf(mm, red[i]);
        bcast = mm;
    }
    __syncthreads();
    m = bcast;

    float sum = 0.f;
    for (int i = tid; i < TT; i += 256) {
        const float e = expf(s[i] - m);
        s[i] = e;
        sum += e;
    }
#pragma unroll
    for (int off = 16; off; off >>= 1)
        sum += __shfl_xor_sync(0xffffffffu, sum, off);
    if ((tid & 31) == 0) red[tid >> 5] = sum;
    __syncthreads();
    if (tid == 0) {
        float t = 0.f;
        for (int i = 0; i < 8; ++i) t += red[i];
        bcast = 1.f / t;
    }
    __syncthreads();
    const float inv = bcast;

    for (int i = tid; i < TT; i += 256) {
        const float wv = s[i] * inv;
        s[i] = wv;
        if (wout) wout[(size_t)b * TT + i] = wv;
    }
}

// ---------------------------------------------------------------------------
// context[b][d] = sum_t weights[b][t] * values[b][t][d]
// ---------------------------------------------------------------------------
__global__ void zero_ctx_kernel(float* __restrict__ ctx) {
    ctx[blockIdx.x * 256 + threadIdx.x] = 0.f;
}

__global__ void ctx_kernel(const float* __restrict__ values,
                           float* __restrict__ ctx) {
    const int b = blockIdx.z;
    const int d = blockIdx.x * 256 + threadIdx.x;
    const int tstart = blockIdx.y * (TT / 16);
    const float* vb = values + (size_t)b * TT * DD;
    const float* w  = g_scores + (size_t)b * TT;

    float acc = 0.f;
#pragma unroll 4
    for (int t = tstart; t < tstart + TT / 16; ++t)
        acc = fmaf(w[t], vb[(size_t)t * DD + d], acc);
    atomicAdd(&ctx[b * DD + d], acc);
}

// ---------------------------------------------------------------------------
extern "C" void kernel_launch(void* const* d_in, const int* in_sizes, int n_in,
                              void* d_out, int out_size) {
    const float* values = (const float*)d_in[0];
    const float* query  = (const float*)d_in[1];
    const float* W1     = (const float*)d_in[2];
    const float* b1     = (const float*)d_in[3];
    const float* W2     = (const float*)d_in[4];
    const float* b2     = (const float*)d_in[5];
    const float* Vv     = (const float*)d_in[6];
    // d_in[7] = bV: constant logit shift, cancels exactly in softmax.

    float* out  = (float*)d_out;
    float* ctx  = nullptr;
    float* wout = nullptr;
    if (out_size >= BB * DD + BB * TT) {
        ctx  = out;
        wout = out + BB * DD;
    } else if (out_size == BB * TT) {
        wout = out;
    } else {
        ctx = out;
    }

    const int smem_bytes = (128 * AP + 32 * BP + 128) * sizeof(float);
    cudaFuncSetAttribute(scores_mma, cudaFuncAttributeMaxDynamicSharedMemorySize,
                         smem_bytes);

    hq_kernel<<<BB, 256>>>(query, W2, b1, b2);
    scores_mma<<<dim3(TT / 128, BB), 512, smem_bytes>>>(values, W1, Vv);
    softmax_kernel<<<BB, 256>>>(wout);
    if (ctx) {
        zero_ctx_kernel<<<(BB * DD) / 256, 256>>>(ctx);
        ctx_kernel<<<dim3(2, 16, BB), 256>>>(values, ctx);
    }
}

// round 4
// speedup vs baseline: 2.4038x; 1.3953x over previous
#include <cuda_runtime.h>
#include <math.h>
#include <stdint.h>

#define BB 32
#define TT 4096
#define DD 512
#define UU 256

#define AP 36     // As pitch (floats)
#define BP 264    // Bs pitch (floats)

// scratch (no allocations allowed)
__device__ float g_hq[BB * UU];
__device__ float g_scores[BB * TT];
__device__ float g_W1r[DD * UU];    // W1, tf32(rna)-rounded, same [k][u] layout

__device__ __forceinline__ float f2tf32f(float f) {
    uint32_t r;
    asm("cvt.rna.tf32.f32 %0, %1;" : "=r"(r) : "f"(f));
    return __uint_as_float(r);
}
__device__ __forceinline__ uint32_t smem_u32(const void* p) {
    uint32_t a;
    asm("{ .reg .u64 t; cvta.to.shared.u64 t, %1; cvt.u32.u64 %0, t; }"
        : "=r"(a) : "l"(p));
    return a;
}
__device__ __forceinline__ void cp_async16(uint32_t dst, const void* src) {
    asm volatile("cp.async.cg.shared.global [%0], [%1], 16;"
                 :: "r"(dst), "l"(src) : "memory");
}
__device__ __forceinline__ void cp_commit() {
    asm volatile("cp.async.commit_group;" ::: "memory");
}
__device__ __forceinline__ void cp_wait0() {
    asm volatile("cp.async.wait_group 0;" ::: "memory");
}
__device__ __forceinline__ void mma_tf32(float c[4], const uint32_t a[4],
                                         const uint32_t b[2]) {
    asm volatile(
        "mma.sync.aligned.m16n8k8.row.col.f32.tf32.tf32.f32 "
        "{%0,%1,%2,%3}, {%4,%5,%6,%7}, {%8,%9}, {%0,%1,%2,%3};"
        : "+f"(c[0]), "+f"(c[1]), "+f"(c[2]), "+f"(c[3])
        : "r"(a[0]), "r"(a[1]), "r"(a[2]), "r"(a[3]), "r"(b[0]), "r"(b[1]));
}

// ---------------------------------------------------------------------------
// g_W1r[k][u] = tf32_rna(W1[k][u])
// ---------------------------------------------------------------------------
__global__ void w1r_kernel(const float* __restrict__ W1) {
    const int i = blockIdx.x * 256 + threadIdx.x;
    g_W1r[i] = f2tf32f(W1[i]);
}

// ---------------------------------------------------------------------------
// hq[b][u] = query[b,:] @ W2[:,u] + b2[u] + b1[u]
// ---------------------------------------------------------------------------
__global__ void hq_kernel(const float* __restrict__ query,
                          const float* __restrict__ W2,
                          const float* __restrict__ b1,
                          const float* __restrict__ b2) {
    __shared__ float q[DD];
    const int b = blockIdx.x;
    const int u = threadIdx.x;
    for (int i = threadIdx.x; i < DD; i += blockDim.x) q[i] = query[b * DD + i];
    __syncthreads();
    float acc = b1[u] + b2[u];
#pragma unroll 8
    for (int d = 0; d < DD; ++d) acc = fmaf(q[d], W2[d * UU + u], acc);
    g_hq[b * UU + u] = acc;
}

// ---------------------------------------------------------------------------
// scores[b][t] = sum_u tanh( values[b,t,:]@W1[:,u] + hq[b][u] ) * V[u]
// tf32 mma.m16n8k8, 128t x 256u full tile per block, K-chunks of 32,
// DOUBLE-BUFFERED: cp.async for W1 (pre-rounded), reg-prefetch+cvt for values.
// 512 threads = 16 warps (2 M x 8 N), 64x32 per warp.
// ---------------------------------------------------------------------------
__global__ __launch_bounds__(512, 1)
void scores_mma(const float* __restrict__ values,
                const float* __restrict__ Vv) {
    extern __shared__ float sm[];
    float* As   = sm;                     // 2 x [128][AP]
    float* Bs   = sm + 2 * 128 * AP;      // 2 x [32][BP]
    float* sred = Bs + 2 * 32 * BP;       // [128]
    const uint32_t Bs_u32 = smem_u32(Bs);

    const int b     = blockIdx.y;
    const int tbase = blockIdx.x * 128;
    const int tid   = threadIdx.x;
    const int lane  = tid & 31;
    const int wid   = tid >> 5;
    const int wm    = wid & 1;
    const int wn    = wid >> 1;
    const int g     = lane >> 2;
    const int tg    = lane & 3;

    const float* vbase = values + ((size_t)b * TT + tbase) * DD;

    // per-thread staging coordinates
    const int at0 = tid >> 3;            // A: rows at0, at0+64 ; col k4a*4
    const int k4a = tid & 7;
    const int bk  = tid >> 4;            // B: row k = bk (k per 16 threads)
    const int bu  = (tid & 15) * 16;     // 4 x 16B starting at float bu*? (16 floats)

    float acc[4][4][4];
#pragma unroll
    for (int i = 0; i < 4; ++i)
#pragma unroll
        for (int j = 0; j < 4; ++j)
#pragma unroll
            for (int c = 0; c < 4; ++c) acc[i][j][c] = 0.f;

    float4 pfA0, pfA1;

    // ---- prologue: stage chunk 0 ----
    {
        const float* w1p = g_W1r + (size_t)bk * UU + bu;
        const uint32_t bdst = Bs_u32 + (bk * BP + bu) * 4;
#pragma unroll
        for (int x = 0; x < 4; ++x) cp_async16(bdst + x * 16, w1p + x * 4);
        cp_commit();
        pfA0 = *(const float4*)(vbase + (size_t)at0 * DD + k4a * 4);
        pfA1 = *(const float4*)(vbase + (size_t)(at0 + 64) * DD + k4a * 4);
        float4 o0, o1;
        o0.x = f2tf32f(pfA0.x); o0.y = f2tf32f(pfA0.y);
        o0.z = f2tf32f(pfA0.z); o0.w = f2tf32f(pfA0.w);
        o1.x = f2tf32f(pfA1.x); o1.y = f2tf32f(pfA1.y);
        o1.z = f2tf32f(pfA1.z); o1.w = f2tf32f(pfA1.w);
        *(float4*)&As[at0 * AP + k4a * 4] = o0;
        *(float4*)&As[(at0 + 64) * AP + k4a * 4] = o1;
        cp_wait0();
    }
    __syncthreads();

    for (int c = 0; c < 16; ++c) {
        const int buf = c & 1;
        const int nxt = buf ^ 1;

        if (c < 15) {
            // issue async staging of chunk c+1
            const int k0n = (c + 1) * 32;
            const float* w1p = g_W1r + (size_t)(k0n + bk) * UU + bu;
            const uint32_t bdst = Bs_u32 + (nxt * 32 * BP + bk * BP + bu) * 4;
#pragma unroll
            for (int x = 0; x < 4; ++x) cp_async16(bdst + x * 16, w1p + x * 4);
            cp_commit();
            pfA0 = *(const float4*)(vbase + (size_t)at0 * DD + k0n + k4a * 4);
            pfA1 = *(const float4*)(vbase + (size_t)(at0 + 64) * DD + k0n + k4a * 4);
        }

        // ---- compute chunk c ----
        const float* Ab = As + buf * 128 * AP;
        const float* Bb = Bs + buf * 32 * BP;
#pragma unroll
        for (int ks = 0; ks < 4; ++ks) {
            const int kk = ks * 8;
            uint32_t a[4][4];
#pragma unroll
            for (int mi = 0; mi < 4; ++mi) {
                const int row = wm * 64 + mi * 16 + g;
                a[mi][0] = __float_as_uint(Ab[row * AP + kk + tg]);
                a[mi][1] = __float_as_uint(Ab[(row + 8) * AP + kk + tg]);
                a[mi][2] = __float_as_uint(Ab[row * AP + kk + 4 + tg]);
                a[mi][3] = __float_as_uint(Ab[(row + 8) * AP + kk + 4 + tg]);
            }
            uint32_t bf[4][2];
#pragma unroll
            for (int nj = 0; nj < 4; ++nj) {
                const int u = wn * 32 + nj * 8 + g;
                bf[nj][0] = __float_as_uint(Bb[(kk + tg) * BP + u]);
                bf[nj][1] = __float_as_uint(Bb[(kk + 4 + tg) * BP + u]);
            }
#pragma unroll
            for (int mi = 0; mi < 4; ++mi)
#pragma unroll
                for (int nj = 0; nj < 4; ++nj)
                    mma_tf32(acc[mi][nj], a[mi], bf[nj]);
        }

        if (c < 15) {
            // finish staging chunk c+1: cvt + STS of A, wait cp.async
            float* An = As + nxt * 128 * AP;
            float4 o0, o1;
            o0.x = f2tf32f(pfA0.x); o0.y = f2tf32f(pfA0.y);
            o0.z = f2tf32f(pfA0.z); o0.w = f2tf32f(pfA0.w);
            o1.x = f2tf32f(pfA1.x); o1.y = f2tf32f(pfA1.y);
            o1.z = f2tf32f(pfA1.z); o1.w = f2tf32f(pfA1.w);
            *(float4*)&An[at0 * AP + k4a * 4] = o0;
            *(float4*)&An[(at0 + 64) * AP + k4a * 4] = o1;
            cp_wait0();
            __syncthreads();
        }
    }

    // ---- epilogue: tanh + dot with V, reduce over u ----
    float sp[4][2];
#pragma unroll
    for (int mi = 0; mi < 4; ++mi) { sp[mi][0] = 0.f; sp[mi][1] = 0.f; }

#pragma unroll
    for (int nj = 0; nj < 4; ++nj) {
        const int u0  = wn * 32 + nj * 8 + 2 * tg;
        const float h0 = g_hq[b * UU + u0];
        const float h1 = g_hq[b * UU + u0 + 1];
        const float v0 = Vv[u0];
        const float v1 = Vv[u0 + 1];
#pragma unroll
        for (int mi = 0; mi < 4; ++mi) {
            sp[mi][0] = fmaf(tanhf(acc[mi][nj][0] + h0), v0, sp[mi][0]);
            sp[mi][0] = fmaf(tanhf(acc[mi][nj][1] + h1), v1, sp[mi][0]);
            sp[mi][1] = fmaf(tanhf(acc[mi][nj][2] + h0), v0, sp[mi][1]);
            sp[mi][1] = fmaf(tanhf(acc[mi][nj][3] + h1), v1, sp[mi][1]);
        }
    }
#pragma unroll
    for (int off = 1; off <= 2; off <<= 1)
#pragma unroll
        for (int mi = 0; mi < 4; ++mi) {
            sp[mi][0] += __shfl_xor_sync(0xffffffffu, sp[mi][0], off);
            sp[mi][1] += __shfl_xor_sync(0xffffffffu, sp[mi][1], off);
        }

    if (tid < 128) sred[tid] = 0.f;
    __syncthreads();
    if (tg == 0) {
#pragma unroll
        for (int mi = 0; mi < 4; ++mi) {
            atomicAdd(&sred[wm * 64 + mi * 16 + g],     sp[mi][0]);
            atomicAdd(&sred[wm * 64 + mi * 16 + g + 8], sp[mi][1]);
        }
    }
    __syncthreads();
    if (tid < 128) g_scores[(size_t)b * TT + tbase + tid] = sred[tid];
}

// ---------------------------------------------------------------------------
// softmax over T per batch
// ---------------------------------------------------------------------------
__global__ void softmax_kernel(float* __restrict__ wout) {
    __shared__ float red[8];
    __shared__ float bcast;
    const int b   = blockIdx.x;
    const int tid = threadIdx.x;
    float* s = g_scores + (size_t)b * TT;

    float m = -3.4e38f;
    for (int i = tid; i < TT; i += 256) m = fmaxf(m, s[i]);
#pragma unroll
    for (int off = 16; off; off >>= 1)
        m = fmaxf(m, __shfl_xor_sync(0xffffffffu, m, off));
    if ((tid & 31) == 0) red[tid >> 5] = m;
    __syncthreads();
    if (tid == 0) {
        float mm = red[0];
        for (int i = 1; i < 8; ++i) mm = fmaxf(mm, red[i]);
        bcast = mm;
    }
    __syncthreads();
    m = bcast;

    float sum = 0.f;
    for (int i = tid; i < TT; i += 256) {
        const float e = expf(s[i] - m);
        s[i] = e;
        sum += e;
    }
#pragma unroll
    for (int off = 16; off; off >>= 1)
        sum += __shfl_xor_sync(0xffffffffu, sum, off);
    if ((tid & 31) == 0) red[tid >> 5] = sum;
    __syncthreads();
    if (tid == 0) {
        float t = 0.f;
        for (int i = 0; i < 8; ++i) t += red[i];
        bcast = 1.f / t;
    }
    __syncthreads();
    const float inv = bcast;

    for (int i = tid; i < TT; i += 256) {
        const float wv = s[i] * inv;
        s[i] = wv;
        if (wout) wout[(size_t)b * TT + i] = wv;
    }
}

// ---------------------------------------------------------------------------
// context[b][d] = sum_t weights[b][t] * values[b][t][d]   (float4 coalesced)
// grid (32 t-splits, B), block 128 (one float4 lane per d4)
// ---------------------------------------------------------------------------
__global__ void zero_ctx_kernel(float* __restrict__ ctx) {
    ctx[blockIdx.x * 256 + threadIdx.x] = 0.f;
}

__global__ void ctx_kernel(const float* __restrict__ values,
                           float* __restrict__ ctx) {
    const int b  = blockIdx.y;
    const int d4 = threadIdx.x;                // 0..127
    const int tstart = blockIdx.x * (TT / 32);
    const float4* vb = (const float4*)(values + (size_t)b * TT * DD) + d4;
    const float*  w  = g_scores + (size_t)b * TT;

    float4 acc = make_float4(0.f, 0.f, 0.f, 0.f);
#pragma unroll 4
    for (int t = tstart; t < tstart + TT / 32; ++t) {
        const float wv = w[t];
        const float4 v = vb[(size_t)t * (DD / 4)];
        acc.x = fmaf(wv, v.x, acc.x);
        acc.y = fmaf(wv, v.y, acc.y);
        acc.z = fmaf(wv, v.z, acc.z);
        acc.w = fmaf(wv, v.w, acc.w);
    }
    float* o = ctx + b * DD + d4 * 4;
    atomicAdd(o + 0, acc.x);
    atomicAdd(o + 1, acc.y);
    atomicAdd(o + 2, acc.z);
    atomicAdd(o + 3, acc.w);
}

// ---------------------------------------------------------------------------
extern "C" void kernel_launch(void* const* d_in, const int* in_sizes, int n_in,
                              void* d_out, int out_size) {
    const float* values = (const float*)d_in[0];
    const float* query  = (const float*)d_in[1];
    const float* W1     = (const float*)d_in[2];
    const float* b1     = (const float*)d_in[3];
    const float* W2     = (const float*)d_in[4];
    const float* b2     = (const float*)d_in[5];
    const float* Vv     = (const float*)d_in[6];
    // d_in[7] = bV: constant logit shift, cancels exactly in softmax.

    float* out  = (float*)d_out;
    float* ctx  = nullptr;
    float* wout = nullptr;
    if (out_size >= BB * DD + BB * TT) {
        ctx  = out;
        wout = out + BB * DD;
    } else if (out_size == BB * TT) {
        wout = out;
    } else {
        ctx = out;
    }

    const int smem_bytes = (2 * 128 * AP + 2 * 32 * BP + 128) * sizeof(float);
    cudaFuncSetAttribute(scores_mma, cudaFuncAttributeMaxDynamicSharedMemorySize,
                         smem_bytes);

    w1r_kernel<<<(DD * UU) / 256, 256>>>(W1);
    hq_kernel<<<BB, 256>>>(query, W2, b1, b2);
    scores_mma<<<dim3(TT / 128, BB), 512, smem_bytes>>>(values, Vv);
    softmax_kernel<<<BB, 256>>>(wout);
    if (ctx) {
        zero_ctx_kernel<<<(BB * DD) / 256, 256>>>(ctx);
        ctx_kernel<<<dim3(32, BB), 128>>>(values, ctx);
    }
}